// round 2
// baseline (speedup 1.0000x reference)
#include <cuda_runtime.h>
#include <cstdint>

// nu_grid_sampler_simple: out[b,c,n] = x[b,c,px,py]
// x: (B=8, C=128, NX=256, NY=256) f32, coords: (B, N=32768, 2) f32 -> out: (B,C,N) f32
//
// R2: the kernel is L1tex-wavefront bound (scattered 4B gathers => one 32B-sector
// wavefront per lane; ~30M wavefronts is irreducible without extra passes that
// cost more DRAM than they save). R1 ran at 52% occupancy (grid too small:
// 1024 blocks) with issue=1.8%. Fix: split the channel loop over gridDim.z=4
// (32 channels per block) -> 4096 blocks, full occupancy, 32 independent
// in-flight LDGs per warp to saturate l1tex.

#define GS_B 8
#define GS_C 128
#define GS_NX 256
#define GS_NY 256
#define GS_N 32768
#define GS_PIX (GS_NX * GS_NY)
#define GS_CCHUNK 32
#define GS_ZSPLIT (GS_C / GS_CCHUNK)   // 4

__global__ __launch_bounds__(256)
void nu_grid_sampler_kernel(const float* __restrict__ x,
                            const float* __restrict__ coords,
                            float* __restrict__ out) {
    const int n  = blockIdx.x * blockDim.x + threadIdx.x;   // point index
    const int b  = blockIdx.y;                               // batch
    const int c0 = blockIdx.z * GS_CCHUNK;                   // channel chunk

    // coalesced 8B load of (coord_y, coord_x)
    const float2 co = reinterpret_cast<const float2*>(coords)[(size_t)b * GS_N + n];

    // replicate reference math: scale by (dim-1), clamp to [0, dim], trunc
    float pxf = fminf(fmaxf(co.y * (float)(GS_NX - 1), 0.0f), (float)GS_NX);
    float pyf = fminf(fmaxf(co.x * (float)(GS_NY - 1), 0.0f), (float)GS_NY);
    int idx = (int)pxf * GS_NY + (int)pyf;
    idx = min(idx, GS_PIX - 1);   // take_along_axis clamp (only hit if coord==1.0)

    const float* __restrict__ xb = x + ((size_t)b * GS_C + c0) * GS_PIX + idx;
    float* __restrict__ ob       = out + ((size_t)b * GS_C + c0) * GS_N + n;

    // 32 independent scattered loads fully in flight per thread; coalesced stores.
    float v[GS_CCHUNK];
    #pragma unroll
    for (int c = 0; c < GS_CCHUNK; ++c)
        v[c] = __ldg(xb + (size_t)c * GS_PIX);
    #pragma unroll
    for (int c = 0; c < GS_CCHUNK; ++c)
        ob[(size_t)c * GS_N] = v[c];
}

extern "C" void kernel_launch(void* const* d_in, const int* in_sizes, int n_in,
                              void* d_out, int out_size) {
    const float* x      = (const float*)d_in[0];   // (8,128,256,256) f32
    const float* coords = (const float*)d_in[1];   // (8,32768,2) f32
    float* out          = (float*)d_out;           // (8,128,32768) f32

    dim3 block(256);
    dim3 grid(GS_N / 256, GS_B, GS_ZSPLIT);        // 128 x 8 x 4 = 4096 blocks
    nu_grid_sampler_kernel<<<grid, block>>>(x, coords, out);
}

// round 3
// speedup vs baseline: 1.8430x; 1.8430x over previous
#include <cuda_runtime.h>
#include <cstdint>

// nu_grid_sampler: out[b,c,n] = x[b,c,px,py], x:(8,128,256,256) f32,
// coords:(8,32768,2) f32, out:(8,128,32768) f32.
//
// R3 strategy: random 4B gathers cost one L1 wavefront per lane (~33.5M total,
// ~126us floor). Instead read every plane densely exactly once: one block per
// (b,c) plane streams the 256KB plane through smem in 4 stages (2x64KB
// cp.async double buffer) and gathers the 32768 points from smem (LDS), with
// fully coalesced stores. DRAM ~= 268MB read + 134MB write -> DRAM-bound.

#define GS_B 8
#define GS_C 128
#define GS_NX 256
#define GS_NY 256
#define GS_N 32768
#define GS_PIX (GS_NX * GS_NY)          // 65536
#define GS_HALF_N (GS_N / 2)            // 16384 pairs
#define STAGE_PIX 16384                  // pixels per smem stage
#define NUM_STAGES (GS_PIX / STAGE_PIX)  // 4
#define K2_THREADS 1024
#define PAIRS_PER_THREAD (GS_HALF_N / K2_THREADS)  // 16

// Packed pixel indices: g_pack[b*16384 + j] = idx(n=j) | (idx(n=j+16384) << 16)
__device__ unsigned int g_pack[GS_B * GS_HALF_N];   // 512 KB static scratch

__device__ __forceinline__ unsigned int compute_idx(float cy, float cx) {
    // reference math: px = trunc(clip(coords[...,1]*(nx-1), 0, nx)), etc.
    float pxf = fminf(fmaxf(cx * (float)(GS_NX - 1), 0.0f), (float)GS_NX);
    float pyf = fminf(fmaxf(cy * (float)(GS_NY - 1), 0.0f), (float)GS_NY);
    int idx = (int)pxf * GS_NY + (int)pyf;
    return (unsigned int)min(idx, GS_PIX - 1);       // take_along_axis clamp
}

__global__ __launch_bounds__(256)
void idx_kernel(const float* __restrict__ coords) {
    int j = blockIdx.x * blockDim.x + threadIdx.x;   // 0..16383
    int b = blockIdx.y;
    const float2* cb = reinterpret_cast<const float2*>(coords) + (size_t)b * GS_N;
    float2 c_lo = cb[j];
    float2 c_hi = cb[j + GS_HALF_N];
    unsigned int lo = compute_idx(c_lo.x, c_lo.y);
    unsigned int hi = compute_idx(c_hi.x, c_hi.y);
    g_pack[b * GS_HALF_N + j] = lo | (hi << 16);
}

__device__ __forceinline__ void cp_async16(void* smem_dst, const void* gmem_src) {
    unsigned int s;
    asm("{ .reg .u64 t; cvta.to.shared.u64 t, %1; cvt.u32.u64 %0, t; }"
        : "=r"(s) : "l"(smem_dst));
    asm volatile("cp.async.cg.shared.global [%0], [%1], 16;\n" :: "r"(s), "l"(gmem_src));
}

__global__ __launch_bounds__(K2_THREADS, 1)
void gather_kernel(const float* __restrict__ x, float* __restrict__ out) {
    extern __shared__ float sbuf[];                  // 2 * STAGE_PIX floats
    const int tid = threadIdx.x;
    const int bc  = blockIdx.x;                      // 0..1023 = b*128 + c
    const int b   = bc >> 7;

    const float* __restrict__ plane = x + ((size_t)bc << 16);   // 65536 f32/plane
    float* __restrict__ ob          = out + ((size_t)bc << 15); // 32768 f32/plane

    // Load this thread's 16 packed index pairs (coalesced, L2-resident)
    unsigned int pair[PAIRS_PER_THREAD];
    const unsigned int* __restrict__ pk = g_pack + b * GS_HALF_N;
    #pragma unroll
    for (int k = 0; k < PAIRS_PER_THREAD; ++k)
        pair[k] = pk[tid + (k << 10)];

    // Prologue: async copy stage 0 -> buf 0 (64KB, 16B per thread per chunk)
    #pragma unroll
    for (int q = 0; q < STAGE_PIX / (K2_THREADS * 4); ++q)       // 4 iters
        cp_async16(&sbuf[(q * K2_THREADS + tid) * 4],
                   &plane[(q * K2_THREADS + tid) * 4]);
    asm volatile("cp.async.commit_group;\n");

    #pragma unroll
    for (int s = 0; s < NUM_STAGES; ++s) {
        float* cur = sbuf + (s & 1) * STAGE_PIX;
        if (s + 1 < NUM_STAGES) {
            float* nxt = sbuf + ((s + 1) & 1) * STAGE_PIX;
            const float* src = plane + (size_t)(s + 1) * STAGE_PIX;
            #pragma unroll
            for (int q = 0; q < STAGE_PIX / (K2_THREADS * 4); ++q)
                cp_async16(&nxt[(q * K2_THREADS + tid) * 4],
                           &src[(q * K2_THREADS + tid) * 4]);
            asm volatile("cp.async.commit_group;\n");
            asm volatile("cp.async.wait_group 1;\n");
        } else {
            asm volatile("cp.async.wait_group 0;\n");
        }
        __syncthreads();

        // Gather all points whose pixel lives in this stage; coalesced stores.
        const unsigned int us = (unsigned int)s;
        #pragma unroll
        for (int k = 0; k < PAIRS_PER_THREAD; ++k) {
            unsigned int pr = pair[k];
            unsigned int lo = pr & 0xFFFFu;
            unsigned int hi = pr >> 16;
            int j = tid + (k << 10);
            if ((lo >> 14) == us) ob[j]             = cur[lo & (STAGE_PIX - 1)];
            if ((hi >> 14) == us) ob[j + GS_HALF_N] = cur[hi & (STAGE_PIX - 1)];
        }
        __syncthreads();   // protect buffer before it is refilled at s+2
    }
}

extern "C" void kernel_launch(void* const* d_in, const int* in_sizes, int n_in,
                              void* d_out, int out_size) {
    const float* x      = (const float*)d_in[0];   // (8,128,256,256) f32
    const float* coords = (const float*)d_in[1];   // (8,32768,2) f32
    float* out          = (float*)d_out;           // (8,128,32768) f32

    static int smem_set = 0;
    if (!smem_set) {
        cudaFuncSetAttribute(gather_kernel,
                             cudaFuncAttributeMaxDynamicSharedMemorySize,
                             2 * STAGE_PIX * sizeof(float));
        smem_set = 1;
    }

    idx_kernel<<<dim3(GS_HALF_N / 256, GS_B), 256>>>(coords);
    gather_kernel<<<GS_B * GS_C, K2_THREADS, 2 * STAGE_PIX * sizeof(float)>>>(x, out);
}